// round 12
// baseline (speedup 1.0000x reference)
#include <cuda_runtime.h>
#include <cuda_fp16.h>
#include <cstdint>

#define B_   2
#define N_   2048
#define DIM_ 768
#define H_   12
#define DH_  64
#define M1   (B_*N_)     // 4096
#define NC1  (3*DIM_)    // 2304
#define KH2  768         // u32 (pair) count per GEMM row
#define PITCHB 3072      // bytes per GEMM row

// ---------------- device globals ----------------
__device__ uint32_t g_xl[(long)M1*KH2];      // x limbs interleaved (h,l)
__device__ uint32_t g_wd[(long)NC1*KH2];     // wqkv dup pairs (w,w)
__device__ uint32_t g_pd[(long)DIM_*KH2];    // wp dup pairs (w,w)
__device__ uint32_t g_zl[(long)M1*KH2];      // z limbs interleaved (attention out)
__device__ __half   g_qh[(long)B_*H_*N_*DH_];   // q single-limb [bh][n][64]
__device__ __half   g_kh[(long)B_*H_*N_*DH_];   // k single-limb [bh][m][64]
__device__ __half   g_vt[(long)B_*H_*DH_*N_];   // v^T single-limb [bh][e][m]
__device__ float    g_bq[NC1];
__device__ float    g_bp2[DIM_];

// ---------------- quantizers ----------------
__device__ __forceinline__ float qround8(float x) {        // round-half-even to 2^-8
    float t = __fmaf_rn(x, 256.f, 12582912.f);
    return (t - 12582912.f) * 0.00390625f;
}
__device__ __forceinline__ float q16_8c(float x) {         // with clamp (z saturates)
    float t = __fmaf_rn(x, 256.f, 12582912.f);
    float y = t - 12582912.f;
    y = fminf(fmaxf(y, -32768.f), 32767.f);
    return y * 0.00390625f;
}
__device__ __forceinline__ float q32_16(float x) {
    float t = __fmaf_rn(x, 65536.f, 12582912.f);
    return (t - 12582912.f) * 1.52587890625e-5f;
}
__device__ __forceinline__ uint32_t packu32(__half a, __half b) {
    __half2 t = __halves2half2(a, b);
    return *(uint32_t*)&t;
}

// ---------------- PTX helpers ----------------
__device__ __forceinline__ uint32_t smem_u32(const void* p) {
    uint32_t a;
    asm("{ .reg .u64 t; cvta.to.shared.u64 t, %1; cvt.u32.u64 %0, t; }" : "=r"(a) : "l"(p));
    return a;
}
#define CP_ASYNC16(dst, src) \
    asm volatile("cp.async.cg.shared.global [%0], [%1], 16;" :: "r"(dst), "l"(src) : "memory")
#define CP_COMMIT() asm volatile("cp.async.commit_group;" ::: "memory")
#define CP_WAIT(n)  asm volatile("cp.async.wait_group %0;" :: "n"(n) : "memory")

__device__ __forceinline__ void ldm_x4(uint32_t* r, uint32_t addr) {
    asm volatile("ldmatrix.sync.aligned.m8n8.x4.shared.b16 {%0,%1,%2,%3}, [%4];"
        : "=r"(r[0]), "=r"(r[1]), "=r"(r[2]), "=r"(r[3]) : "r"(addr));
}
__device__ __forceinline__ void mma16816(float* d, const uint32_t* a, const uint32_t* b) {
    asm volatile("mma.sync.aligned.m16n8k16.row.col.f32.f16.f16.f32 "
        "{%0,%1,%2,%3}, {%4,%5,%6,%7}, {%8,%9}, {%0,%1,%2,%3};"
        : "+f"(d[0]), "+f"(d[1]), "+f"(d[2]), "+f"(d[3])
        : "r"(a[0]), "r"(a[1]), "r"(a[2]), "r"(a[3]), "r"(b[0]), "r"(b[1]));
}

// 128B-pitch swizzle: XOR 16B-chunk id with row%8
#define SWZ(row, colb) ((uint32_t)((row)*128 + ((colb) ^ (((row)&7)<<4))))

// ---------------- kernel 1: quantize + limb-split inputs ----------------
__global__ void prep_kernel(const float* __restrict__ x, const float* __restrict__ wqkv,
                            const float* __restrict__ bqkv, const float* __restrict__ wp,
                            const float* __restrict__ bp) {
    long i = (long)blockIdx.x * blockDim.x + threadIdx.x;
    const long NX = (long)M1 * DIM_;
    const long NW = (long)NC1 * DIM_;
    const long NP = (long)DIM_ * DIM_;
    if (i < NX) {
        float v = q32_16(x[i]);
        __half h = __float2half_rn(v);
        __half l = __float2half_rn(v - __half2float(h));
        g_xl[i] = packu32(h, l);
        return;
    }
    i -= NX;
    if (i < NW) {
        __half h = __float2half_rn(qround8(wqkv[i]));   // exact: |w*256| << 2048
        g_wd[i] = packu32(h, h);
        return;
    }
    i -= NW;
    if (i < NP) {
        __half h = __float2half_rn(qround8(wp[i]));
        g_pd[i] = packu32(h, h);
        return;
    }
    i -= NP;
    if (i < NC1) { g_bq[i] = qround8(bqkv[i]); return; }
    i -= NC1;
    if (i < DIM_) g_bp2[i] = qround8(bp[i]);
}

// ---------------- QKV GEMM core: 3-stage single-sync (M=128 tile) ----------------
#define GSTG 32768   // A 16KB + B 16KB per stage
struct AccTile { float a[2][8][4]; };

__device__ __forceinline__ void gemm_issue(uint32_t st, const char* Ab, const char* Bb,
                                           int kbyte, int tid) {
    #pragma unroll
    for (int i = 0; i < 4; i++) {
        int idx = tid + i * 256;
        int row = idx >> 3, c16 = (idx & 7) << 4;
        CP_ASYNC16(st + SWZ(row, c16), Ab + (long)row * PITCHB + kbyte + c16);
    }
    #pragma unroll
    for (int i = 0; i < 4; i++) {
        int idx = tid + i * 256;
        int row = idx >> 3, c16 = (idx & 7) << 4;
        CP_ASYNC16(st + 16384 + SWZ(row, c16), Bb + (long)row * PITCHB + kbyte + c16);
    }
    CP_COMMIT();
}

__device__ __forceinline__ void gemm_compute(uint32_t st, AccTile& acc, int wm, int wn, int lane) {
    const int arow_l = (lane & 7) + ((lane >> 3) & 1) * 8;
    const int achk   = (lane >> 4) * 16;
    const int brow_l = (lane & 7) + (lane >> 4) * 8;
    const int bchk   = ((lane >> 3) & 1) * 16;
    #pragma unroll
    for (int kk = 0; kk < 4; kk++) {
        uint32_t a[2][4];
        #pragma unroll
        for (int f = 0; f < 2; f++)
            ldm_x4(a[f], st + SWZ(wm * 32 + f * 16 + arow_l, kk * 32 + achk));
        #pragma unroll
        for (int g = 0; g < 4; g++) {
            uint32_t b4[4];
            ldm_x4(b4, st + 16384 + SWZ(wn * 64 + g * 16 + brow_l, kk * 32 + bchk));
            #pragma unroll
            for (int f = 0; f < 2; f++) {
                mma16816(acc.a[f][g * 2 + 0], a[f], b4 + 0);
                mma16816(acc.a[f][g * 2 + 1], a[f], b4 + 2);
            }
        }
    }
}

__device__ __forceinline__ void gemm_main(const char* Ab, const char* Bb,
                                          AccTile& acc, char* smem, int tid) {
    uint32_t sb = smem_u32(smem);
    const int lane = tid & 31, wid = tid >> 5;
    const int wm = wid & 3, wn = wid >> 2;
    #pragma unroll
    for (int f = 0; f < 2; f++)
        #pragma unroll
        for (int j = 0; j < 8; j++)
            #pragma unroll
            for (int e = 0; e < 4; e++) acc.a[f][j][e] = 0.f;

    gemm_issue(sb + 0 * GSTG, Ab, Bb, 0, tid);
    gemm_issue(sb + 1 * GSTG, Ab, Bb, 128, tid);
    #pragma unroll 1
    for (int g = 0; g < 24; g++) {
        if (g + 2 < 24) { CP_WAIT(1); } else { CP_WAIT(0); }
        __syncthreads();
        if (g + 2 < 24)
            gemm_issue(sb + (uint32_t)((g + 2) % 3) * GSTG, Ab, Bb, (g + 2) * 128, tid);
        gemm_compute(sb + (uint32_t)(g % 3) * GSTG, acc, wm, wn, lane);
    }
}

// ---------------- kernel 2: QKV projection + single-limb q/k/v epilogue ----------------
__global__ void __launch_bounds__(256, 2) gemm_qkv_tc() {
    extern __shared__ char smem[];
    const int tid = threadIdx.x;
    const int m0 = blockIdx.y * 128;
    const int n0 = blockIdx.x * 128;
    AccTile acc;
    gemm_main((const char*)g_xl + (long)m0 * PITCHB,
              (const char*)g_wd + (long)n0 * PITCHB, acc, smem, tid);

    const int wid = tid >> 5, lane = tid & 31;
    const int wm = wid & 3, wn = wid >> 2;
    const int rb = m0 + wm * 32 + (lane >> 2);
    const int cb = n0 + wn * 64 + (lane & 3) * 2;
    #pragma unroll
    for (int f = 0; f < 2; f++) {
        #pragma unroll
        for (int j = 0; j < 8; j++) {
            int nb = cb + j * 8;                 // even
            float b0 = g_bq[nb], b1 = g_bq[nb + 1];
            int h = nb / 192;
            int rr = nb - h * 192;
            int seg = rr >> 6, e = rr & 63;      // e even
            #pragma unroll
            for (int rs = 0; rs < 2; rs++) {
                int m = rb + f * 16 + rs * 8;
                int bi = m >> 11, nr = m & 2047;
                long bh = bi * H_ + h;
                __half h0 = __float2half_rn(qround8(acc.a[f][j][rs * 2 + 0] + b0));
                __half h1 = __float2half_rn(qround8(acc.a[f][j][rs * 2 + 1] + b1));
                if (seg == 0) {
                    *(uint32_t*)(g_qh + (bh * N_ + nr) * DH_ + e) = packu32(h0, h1);
                } else if (seg == 1) {
                    *(uint32_t*)(g_kh + (bh * N_ + nr) * DH_ + e) = packu32(h0, h1);
                } else {
                    g_vt[(bh * DH_ + e) * N_ + nr] = h0;
                    g_vt[(bh * DH_ + e + 1) * N_ + nr] = h1;
                }
            }
        }
    }
}

// ---------------- kernel 4: output projection, M=64 tile, 4-stage ----------------
#define PSTG 24576   // A 8KB + B 16KB per stage

__device__ __forceinline__ void proj_issue(uint32_t st, const char* Ab, const char* Bb,
                                           int kbyte, int tid) {
    #pragma unroll
    for (int i = 0; i < 2; i++) {
        int idx = tid + i * 256;
        int row = idx >> 3, c16 = (idx & 7) << 4;
        CP_ASYNC16(st + SWZ(row, c16), Ab + (long)row * PITCHB + kbyte + c16);
    }
    #pragma unroll
    for (int i = 0; i < 4; i++) {
        int idx = tid + i * 256;
        int row = idx >> 3, c16 = (idx & 7) << 4;
        CP_ASYNC16(st + 8192 + SWZ(row, c16), Bb + (long)row * PITCHB + kbyte + c16);
    }
    CP_COMMIT();
}

__global__ void __launch_bounds__(256, 2) gemm_proj_tc(float* __restrict__ out) {
    extern __shared__ char smem[];
    const uint32_t sb = smem_u32(smem);
    const int tid = threadIdx.x, lane = tid & 31, wid = tid >> 5;
    const int wm = wid & 1, wn = wid >> 1;       // 2 m-groups x 4 n-groups, warp tile 32x32
    const int m0 = blockIdx.y * 64;
    const int n0 = blockIdx.x * 128;
    const char* Ab = (const char*)g_zl + (long)m0 * PITCHB;
    const char* Bb = (const char*)g_pd + (long)n0 * PITCHB;

    const int arow_l = (lane & 7) + ((lane >> 3) & 1) * 8;
    const int achk   = (lane >> 4) * 16;
    const int brow_l = (lane & 7) + (lane >> 4) * 8;
    const int bchk   = ((lane >> 3) & 1) * 16;

    float acc[2][4][4];
    #pragma unroll
    for (int f = 0; f < 2; f++)
        #pragma unroll
        for (int j = 0; j < 4; j++)
            #pragma unroll
            for (int e = 0; e < 4; e++) acc[f][j][e] = 0.f;

    proj_issue(sb + 0 * PSTG, Ab, Bb, 0, tid);
    proj_issue(sb + 1 * PSTG, Ab, Bb, 128, tid);
    proj_issue(sb + 2 * PSTG, Ab, Bb, 256, tid);
    #pragma unroll 1
    for (int g = 0; g < 24; g++) {
        if (g + 3 < 24) { CP_WAIT(2); } else { CP_WAIT(0); }
        __syncthreads();
        if (g + 3 < 24)
            proj_issue(sb + (uint32_t)((g + 3) & 3) * PSTG, Ab, Bb, (g + 3) * 128, tid);
        uint32_t st = sb + (uint32_t)(g & 3) * PSTG;
        #pragma unroll
        for (int kk = 0; kk < 4; kk++) {
            uint32_t a[2][4];
            #pragma unroll
            for (int f = 0; f < 2; f++)
                ldm_x4(a[f], st + SWZ(wm * 32 + f * 16 + arow_l, kk * 32 + achk));
            #pragma unroll
            for (int gg = 0; gg < 2; gg++) {
                uint32_t b4[4];
                ldm_x4(b4, st + 8192 + SWZ(wn * 32 + gg * 16 + brow_l, kk * 32 + bchk));
                #pragma unroll
                for (int f = 0; f < 2; f++) {
                    mma16816(acc[f][gg * 2 + 0], a[f], b4 + 0);
                    mma16816(acc[f][gg * 2 + 1], a[f], b4 + 2);
                }
            }
        }
    }

    const int rb = m0 + wm * 32 + (lane >> 2);
    const int cb = n0 + wn * 32 + (lane & 3) * 2;
    #pragma unroll
    for (int f = 0; f < 2; f++)
        #pragma unroll
        for (int j = 0; j < 4; j++)
            #pragma unroll
            for (int cs = 0; cs < 2; cs++) {
                int n = cb + j * 8 + cs;
                float bias = g_bp2[n];
                #pragma unroll
                for (int rs = 0; rs < 2; rs++) {
                    int m = rb + f * 16 + rs * 8;
                    out[(long)m * DIM_ + n] = qround8(acc[f][j][rs * 2 + cs] + bias);
                }
            }
}

// ---------------- kernel 3: register-resident flash attention ----------------
// s never touches smem: phase-1 C frags are re-quantized in registers and used
// directly as phase-2 A frags (C/A layout identity for m16n8k16).
// Each warp (wm,wn): phase1 s[wm 32 rows][wn 32-col k-half]; phase2 z over its
// k-half for ALL 64 e-cols. Cross-wn partial sum once at the end via smem.
// smem: Q 16K | KV 3 stages x 16K = 64KB total.
#define AQ    0u
#define AKV   16384u
#define ASTG  16384u
#define ATTN_SMEM 65536

__device__ __forceinline__ void attn_issue(uint32_t stage_base,
        const char* khb, const char* vtb, int kb, int tid) {
    #pragma unroll
    for (int i = 0; i < 2; i++) {
        int idx = tid + i * 256;
        int row = idx >> 3, c16 = (idx & 7) << 4;
        CP_ASYNC16(stage_base + SWZ(row, c16), khb + (long)(kb + row) * 128 + c16);
    }
    #pragma unroll
    for (int i = 0; i < 2; i++) {
        int idx = tid + i * 256;
        int row = idx >> 3, c16 = (idx & 7) << 4;
        CP_ASYNC16(stage_base + 8192 + SWZ(row, c16), vtb + (long)row * (N_ * 2) + kb * 2 + c16);
    }
    CP_COMMIT();
}

__global__ void __launch_bounds__(256, 1) attn_tc_kernel() {
    extern __shared__ char smem[];
    const uint32_t sb = smem_u32(smem);
    const int tid = threadIdx.x;
    const int lane = tid & 31, wid = tid >> 5;
    const int wm = wid & 3, wn = wid >> 2;   // wm: q-row group of 32; wn: k-half
    const int bh = blockIdx.y;
    const int q0 = blockIdx.x * 128;

    const char* qhb = (const char*)(g_qh + ((long)bh * N_ + q0) * DH_);
    const char* khb = (const char*)(g_kh + (long)bh * N_ * DH_);
    const char* vtb = (const char*)(g_vt + (long)bh * DH_ * N_);

    // prologue: Q tile + stages 0,1
    #pragma unroll
    for (int i = 0; i < 4; i++) {
        int idx = tid + i * 256;
        int row = idx >> 3, c16 = (idx & 7) << 4;
        CP_ASYNC16(sb + AQ + SWZ(row, c16), qhb + (long)row * 128 + c16);
    }
    attn_issue(sb + AKV + 0 * ASTG, khb, vtb, 0, tid);
    attn_issue(sb + AKV + 1 * ASTG, khb, vtb, 64, tid);

    const int arow_l = (lane & 7) + ((lane >> 3) & 1) * 8;
    const int achk   = (lane >> 4) * 16;
    const int brow_l = (lane & 7) + (lane >> 4) * 8;
    const int bchk   = ((lane >> 3) & 1) * 16;
    const int qr     = lane >> 2;
    const int qc     = (lane & 3) * 2;

    uint32_t qfrag[4][2][4];   // Q fragments, loop-invariant
    float zacc[2][8][4];       // z partial over this warp's k-half, all 64 e
    #pragma unroll
    for (int f = 0; f < 2; f++)
        #pragma unroll
        for (int j = 0; j < 8; j++)
            #pragma unroll
            for (int e = 0; e < 4; e++) zacc[f][j][e] = 0.f;

    #pragma unroll 1
    for (int it = 0; it < 32; it++) {
        if (it + 2 < 32) { CP_WAIT(1); } else { CP_WAIT(0); }
        __syncthreads();
        if (it + 2 < 32)
            attn_issue(sb + AKV + (uint32_t)((it + 2) % 3) * ASTG, khb, vtb, (it + 2) * 64, tid);
        const uint32_t sK = sb + AKV + (uint32_t)(it % 3) * ASTG;
        const uint32_t sV = sK + 8192u;

        if (it == 0) {
            #pragma unroll
            for (int kk = 0; kk < 4; kk++)
                #pragma unroll
                for (int f = 0; f < 2; f++)
                    ldm_x4(qfrag[kk][f], sb + AQ + SWZ(wm * 32 + f * 16 + arow_l, kk * 32 + achk));
        }

        // ---- phase 1: s[wm 32 rows][wn 32 cols] = q x k^T over e=64 ----
        float sacc[2][4][4];
        #pragma unroll
        for (int f = 0; f < 2; f++)
            #pragma unroll
            for (int j = 0; j < 4; j++)
                #pragma unroll
                for (int e = 0; e < 4; e++) sacc[f][j][e] = 0.f;
        #pragma unroll
        for (int kk = 0; kk < 4; kk++) {
            #pragma unroll
            for (int g = 0; g < 2; g++) {
                uint32_t b4[4];
                ldm_x4(b4, sK + SWZ(wn * 32 + g * 16 + brow_l, kk * 32 + bchk));
                #pragma unroll
                for (int f = 0; f < 2; f++) {
                    mma16816(sacc[f][g * 2 + 0], qfrag[kk][f], b4 + 0);
                    mma16816(sacc[f][g * 2 + 1], qfrag[kk][f], b4 + 2);
                }
            }
        }

        // ---- quantize s in registers -> A-fragments (hi/lo limb planes) ----
        // C/A identity: A-frag reg{0,1,2,3} for k-chunk c = C tiles {2c(c0c1),2c(c2c3),2c+1(c0c1),2c+1(c2c3)}
        uint32_t shi[2][2][4], slo[2][2][4];   // [f][c][reg]
        #pragma unroll
        for (int f = 0; f < 2; f++)
            #pragma unroll
            for (int c = 0; c < 2; c++)
                #pragma unroll
                for (int r = 0; r < 4; r++) {
                    int j = 2 * c + (r >> 1);
                    int e0 = (r & 1) * 2;
                    float s0 = qround8(sacc[f][j][e0 + 0]);
                    float s1 = qround8(sacc[f][j][e0 + 1]);
                    __half h0 = __float2half_rn(s0);
                    __half h1 = __float2half_rn(s1);
                    __half l0 = __float2half_rn(s0 - __half2float(h0));
                    __half l1 = __float2half_rn(s1 - __half2float(h1));
                    shi[f][c][r] = packu32(h0, h1);
                    slo[f][c][r] = packu32(l0, l1);
                }

        // ---- phase 2: z += s x v over this warp's k-half, all 64 e ----
        #pragma unroll
        for (int c = 0; c < 2; c++) {
            #pragma unroll
            for (int g = 0; g < 4; g++) {
                uint32_t bv[4];
                ldm_x4(bv, sV + SWZ(g * 16 + brow_l, (2 * wn + c) * 32 + bchk));
                #pragma unroll
                for (int f = 0; f < 2; f++) {
                    mma16816(zacc[f][g * 2 + 0], shi[f][c], bv + 0);
                    mma16816(zacc[f][g * 2 + 1], shi[f][c], bv + 2);
                    mma16816(zacc[f][g * 2 + 0], slo[f][c], bv + 0);
                    mma16816(zacc[f][g * 2 + 1], slo[f][c], bv + 2);
                }
            }
        }
    }

    // ---- cross-wn partial reduction (once) + epilogue ----
    __syncthreads();                      // stages no longer needed
    float* xch = (float*)(smem + AKV);    // [128][68] floats = 34816 B
    if (wn == 1) {
        #pragma unroll
        for (int f = 0; f < 2; f++)
            #pragma unroll
            for (int j = 0; j < 8; j++)
                #pragma unroll
                for (int rs = 0; rs < 2; rs++) {
                    int row = wm * 32 + f * 16 + qr + rs * 8;
                    int col = j * 8 + qc;
                    xch[row * 68 + col]     = zacc[f][j][rs * 2 + 0];
                    xch[row * 68 + col + 1] = zacc[f][j][rs * 2 + 1];
                }
    }
    __syncthreads();
    if (wn == 0) {
        const int b = bh / H_, h = bh - b * H_;
        #pragma unroll
        for (int f = 0; f < 2; f++)
            #pragma unroll
            for (int j = 0; j < 8; j++)
                #pragma unroll
                for (int rs = 0; rs < 2; rs++) {
                    int row = wm * 32 + f * 16 + qr + rs * 8;
                    int n = q0 + row;
                    #pragma unroll
                    for (int cs = 0; cs < 2; cs++) {
                        int e = j * 8 + qc + cs;
                        float zq = q16_8c(zacc[f][j][rs * 2 + cs] + xch[row * 68 + e]);
                        __half hh = __float2half_rn(zq);
                        __half ll = __float2half_rn(zq - __half2float(hh));
                        g_zl[((long)(b * N_ + n)) * KH2 + h * DH_ + e] = packu32(hh, ll);
                    }
                }
    }
}

// ---------------- launch ----------------
extern "C" void kernel_launch(void* const* d_in, const int* in_sizes, int n_in,
                              void* d_out, int out_size) {
    const float* q_in = (const float*)d_in[0];
    const float* wqkv = (const float*)d_in[1];
    const float* bqkv = (const float*)d_in[2];
    const float* wp   = (const float*)d_in[3];
    const float* bp   = (const float*)d_in[4];
    float* out = (float*)d_out;

    const long total = (long)M1 * DIM_ + (long)NC1 * DIM_ + (long)DIM_ * DIM_ + NC1 + DIM_;
    prep_kernel<<<(unsigned)((total + 255) / 256), 256>>>(q_in, wqkv, bqkv, wp, bp);

    const int gemm_smem = 3 * GSTG;   // 98304 -> 2 CTA/SM
    cudaFuncSetAttribute(gemm_qkv_tc, cudaFuncAttributeMaxDynamicSharedMemorySize, gemm_smem);
    gemm_qkv_tc<<<dim3(NC1 / 128, M1 / 128), 256, gemm_smem>>>();       // (18, 32)

    cudaFuncSetAttribute(attn_tc_kernel, cudaFuncAttributeMaxDynamicSharedMemorySize, ATTN_SMEM);
    attn_tc_kernel<<<dim3(N_ / 128, B_ * H_), 256, ATTN_SMEM>>>();      // (16, 24)

    const int proj_smem = 4 * PSTG;   // 98304 -> 2 CTA/SM
    cudaFuncSetAttribute(gemm_proj_tc, cudaFuncAttributeMaxDynamicSharedMemorySize, proj_smem);
    gemm_proj_tc<<<dim3(DIM_ / 128, M1 / 64), 256, proj_smem>>>(out);   // (6, 64)
}